// round 6
// baseline (speedup 1.0000x reference)
#include <cuda_runtime.h>

// RelativePosition: out[b, k(i,j)] = a[b,j] - a[b,i], j > i, row-major strict
// upper triangle. Row i = contiguous segment: base(i) = i*(n-1) - i*(i-1)/2,
// len = n-1-i, out[base+t] = a[i+1+t] - a[i].
//
// R6: register-resident source windows (kill per-iteration LDS -> L1 port).
//  * Warp owns source window [W, W+132): lane l holds a[W+4l .. W+4l+7]
//    in two float4 regs (loaded once per 16 rows via LDG, L1-resident).
//  * Output float4 f of row i has source j = 4f - base_i + i + 1. Window w
//    takes f with source start in [W, W+128): f in [F0, F0+32),
//    F0 = ceil(S/4), S = base_i + W - i - 1, shift h = (-S)&3.
//    Lane l's 4 sources = window-relative [h+4l, h+4l+3] -> subset of its
//    own 8 regs for ANY h in 0..3. Warp-uniform 4-way select, 4 FADD,
//    1 predicated streaming STG.128. Zero LDS/SHFL per store.
//  * Windows tile exactly: F0(w+1) = F0(w)+32. Predicate clips to the row's
//    interior float4 range [fb, fe).
//  * Row head scalars (<=3) written by window w == (i+1)>>7; tail scalars
//    by the last window; sources via direct LDG (input is L1-resident).
//  * a[i] per row: lane-preloaded, broadcast with 1 SHFL.

#define TPB 256
#define WSH 7
#define WW  128            // window width (floats)

__global__ void __launch_bounds__(TPB)
relpos_kernel(const float* __restrict__ in, float* __restrict__ out,
              int n, int P, int NW, int BPB)
{
    // ---- decode blockIdx -> (batch b, window w, row-chunk) ----
    int b = blockIdx.x / BPB;
    int r = blockIdx.x - b * BPB;
    int w = 0, chunk = 0;
    {
        int acc = 0;
        #pragma unroll
        for (int ww = 0; ww < 8; ++ww) {           // NW == 8 for n=1024
            if (ww >= NW) break;
            int Imax = min(ww * WW + WW - 2, n - 2);
            int C = (Imax + WW) >> WSH;            // chunks of WW rows
            if (r < acc + C) { w = ww; chunk = r - acc; break; }
            acc += C;
        }
    }

    const int tid = threadIdx.x, wid = tid >> 5, lid = tid & 31;
    const float* __restrict__ arow = in + b * n;
    float* __restrict__ outb = out + b * P;

    const int W = w * WW;
    const int Imax = min(W + WW - 2, n - 2);
    int i0 = chunk * WW + wid * 16;                // 16 rows per warp
    if (i0 > Imax) return;                          // warp-uniform exit
    int iend = min(i0 + 16, Imax + 1);

    // ---- source window registers: lane l holds a[W+4l .. W+4l+7] ----
    float4 e0 = *(const float4*)(arow + W + 4 * lid);
    int o1 = W + 4 * lid + 4;
    if (o1 > n - 4) o1 = n - 4;                     // clamp (clamped part unread)
    float4 e1 = *(const float4*)(arow + o1);

    // ---- preload a[i] for this warp's 16 rows (lanes 0..15) ----
    int il = i0 + lid;
    if (il > n - 2) il = n - 2;
    float a_pre = arow[il];

    const bool lastw = (w == NW - 1);

    int i    = i0;
    int base = i * (n - 1) - ((i * (i - 1)) >> 1);
    int S    = base + W - i - 1;
    int len  = n - 1 - i;

    for (; i < iend; ++i) {
        float ai = __shfl_sync(0xffffffffu, a_pre, i - i0);

        int F0 = (S + 3) >> 2;                      // ceil(S/4), S may be -1
        int hp = (-S) & 3;                          // alignment shift 0..3
        int fb = (base + 3) >> 2;                   // row interior f range
        int fe = (base + len) >> 2;
        int f  = F0 + lid;
        bool pv = (f >= fb) && (f < fe);

        float4 o;
        switch (hp) {                               // warp-uniform
            case 0:  o = make_float4(e0.x - ai, e0.y - ai, e0.z - ai, e0.w - ai); break;
            case 1:  o = make_float4(e0.y - ai, e0.z - ai, e0.w - ai, e1.x - ai); break;
            case 2:  o = make_float4(e0.z - ai, e0.w - ai, e1.x - ai, e1.y - ai); break;
            default: o = make_float4(e0.w - ai, e1.x - ai, e1.y - ai, e1.z - ai); break;
        }
        if (pv) __stcs((float4*)outb + f, o);

        // ---- head scalars: assigned uniquely to window (i+1)>>WSH ----
        if (((i + 1) >> WSH) == w) {
            int h0 = (-base) & 3;
            if (h0 > len) h0 = len;
            if (lid < h0)
                outb[base + lid] = __ldg(arow + i + 1 + lid) - ai;
        }
        // ---- tail scalars: assigned to the last window ----
        if (lastw) {
            int h0 = (-base) & 3;
            if (h0 > len) h0 = len;
            int tl = (base + len) & 3;
            int rem = len - h0;
            if (tl > rem) tl = rem;
            if (lid < tl)
                outb[base + len - 1 - lid] = __ldg(arow + n - 1 - lid) - ai;
        }

        // ---- advance to next row ----
        S += n - 2 - i;
        base += len;
        --len;
    }
}

extern "C" void kernel_launch(void* const* d_in, const int* in_sizes, int n_in,
                              void* d_out, int out_size)
{
    const float* in = (const float*)d_in[0];
    float* out = (float*)d_out;

    long long total_in = in_sizes[0];                        // B * n
    int n = (int)(2LL * (long long)out_size / total_in + 1); // 1024
    int B = (int)(total_in / n);                             // 128
    int P = n * (n - 1) / 2;                                 // 523776 < 2^31

    int NW = n >> WSH;                                       // 8 windows
    int BPB = 0;                                             // blocks per batch
    for (int w = 0; w < NW; ++w) {
        int Imax = (w * WW + WW - 2 < n - 2) ? (w * WW + WW - 2) : (n - 2);
        BPB += (Imax + WW) >> WSH;
    }                                                        // = 36 for n=1024

    relpos_kernel<<<B * BPB, TPB>>>(in, out, n, P, NW, BPB);
}